// round 11
// baseline (speedup 1.0000x reference)
#include <cuda_runtime.h>
#include <cuda_bf16.h>
#include <math.h>

#define MAXN 50000
#define MAXE 800000

// ---------------- device scratch (static zero-init covers first call) ----------------
__device__ __align__(16) float g_qt [(size_t)MAXN * 128];       // x@(WqWk^T) + gvec
__device__ __align__(16) __nv_bfloat16 g_xb[(size_t)MAXN * 64]; // x in bf16 (gather side)
__device__ __align__(16) __nv_bfloat16 g_v [(size_t)MAXN * 128];// projected v, bf16
__device__ __align__(16) float g_agg[(size_t)MAXN * 128];       // attention output
__device__ __align__(16) float g_M  [64 * 128];                 // Mcat = Wq Wk^T per head
__device__ __align__(16) float g_W2 [64 * 64];                  // Wskip @ Wc
__device__ float  g_gvec[128];                                   // Wk_h @ bq_h per head
__device__ float  g_b2[64];                                      // bskip@Wc + bc
__device__ int    g_esrc [MAXE];
__device__ int    g_edst [MAXE];
__device__ int    g_srcs [MAXE];
__device__ int    g_cnt  [MAXN];   // zeroed by previous call's k_norm (or static init)
__device__ int    g_cur  [MAXN];   // ditto
__device__ int    g_rowptr[MAXN + 1];
__device__ double g_stats[2];      // zeroed in k_cvprep tail each call

// ================= launch 1: convert(+hist) + precomputes + stats zero =================
__global__ void k_cvprep(const void* __restrict__ ei, int e,
                         const float* __restrict__ Wq, const float* __restrict__ bq,
                         const float* __restrict__ Wk,
                         const float* __restrict__ Wsk, const float* __restrict__ bsk,
                         const float* __restrict__ Wc, const float* __restrict__ bc) {
    int nconv = (2 * e + 255) >> 8;
    if ((int)blockIdx.x < nconv) {
        // ---- edge convert (self-detecting dtype) + fused dst histogram ----
        __shared__ int s_is64;
        if (threadIdx.x == 0) {
            const int* w = (const int*)ei;
            int all0 = 1;
            for (int i = 1; i < 64; i += 2) all0 &= (w[i] == 0);
            s_is64 = all0;
        }
        __syncthreads();
        int i = blockIdx.x * 256 + threadIdx.x;
        if (i >= 2 * e) return;
        int v;
        if (s_is64) v = (int)((const long long*)ei)[i];
        else        v = ((const int*)ei)[i];
        if (i < e) g_esrc[i] = v;
        else { g_edst[i - e] = v; atomicAdd(&g_cnt[v], 1); }
        return;
    }
    // ---- precomputes: 8 threads/output + shuffle reduce ----
    int idx = (blockIdx.x - nconv) * 256 + threadIdx.x;
    if (idx == 0) { g_stats[0] = 0.0; g_stats[1] = 0.0; }
    int g = idx >> 3, part = idx & 7;
    float s = 0.f;
    int valid = 0;
    float* dst = 0;
    if (g < 8192) {                      // Mcat[i][h*64+j] = sum_c Wq[i][h64+c]*Wk[j][h64+c]
        int i = g >> 7, col = g & 127, h = col >> 6, j = col & 63;
        const float* wq = Wq + i * 128 + h * 64 + part * 8;
        const float* wk = Wk + j * 128 + h * 64 + part * 8;
#pragma unroll
        for (int c = 0; c < 8; c++) s = fmaf(wq[c], wk[c], s);
        dst = &g_M[g]; valid = 1;
    } else if (g < 12288) {              // W2 = Wskip @ Wc
        int o = g - 8192, r = o >> 6, c = o & 63;
#pragma unroll
        for (int k = 0; k < 16; k++)
            s = fmaf(Wsk[r * 128 + part * 16 + k], Wc[(part * 16 + k) * 64 + c], s);
        dst = &g_W2[o]; valid = 1;
    } else if (g < 12352) {              // b2 = bskip@Wc + bc
        int c = g - 12288;
        if (part == 0) s = bc[c];
#pragma unroll
        for (int k = 0; k < 16; k++)
            s = fmaf(bsk[part * 16 + k], Wc[(part * 16 + k) * 64 + c], s);
        dst = &g_b2[c]; valid = 1;
    } else if (g < 12480) {              // gvec[h*64+i] = sum_j Wk[i][h64+j]*bq[h64+j]
        int o = g - 12352, h = o >> 6, i = o & 63;
#pragma unroll
        for (int j = 0; j < 8; j++)
            s = fmaf(Wk[i * 128 + h * 64 + part * 8 + j], bq[h * 64 + part * 8 + j], s);
        dst = &g_gvec[o]; valid = 1;
    }
    s += __shfl_xor_sync(0xffffffffu, s, 1);
    s += __shfl_xor_sync(0xffffffffu, s, 2);
    s += __shfl_xor_sync(0xffffffffu, s, 4);
    if (valid && part == 0) *dst = s;
}

// ================= launch 2: single-block exclusive scan (warp-shuffle based) =================
__global__ void __launch_bounds__(1024) k_scan(int n) {
    __shared__ int warpsum[32];
    int tid = threadIdx.x;
    int lane = tid & 31, wid = tid >> 5;
    int carry = 0;
    int nchunk = (n + 1023) >> 10;
    for (int c = 0; c < nchunk; c++) {
        int i = (c << 10) + tid;
        int v = (i < n) ? g_cnt[i] : 0;
        // inclusive warp scan
        int s = v;
#pragma unroll
        for (int off = 1; off < 32; off <<= 1) {
            int t = __shfl_up_sync(0xffffffffu, s, off);
            if (lane >= off) s += t;
        }
        if (lane == 31) warpsum[wid] = s;
        __syncthreads();
        if (wid == 0) {
            int ws = warpsum[lane];
#pragma unroll
            for (int off = 1; off < 32; off <<= 1) {
                int t = __shfl_up_sync(0xffffffffu, ws, off);
                if (lane >= off) ws += t;
            }
            warpsum[lane] = ws;
        }
        __syncthreads();
        int base = (wid > 0) ? warpsum[wid - 1] : 0;
        if (i < n) g_rowptr[i] = carry + base + s - v;   // exclusive
        carry += warpsum[31];
        __syncthreads();   // protect warpsum before next chunk overwrites
    }
    if (tid == 0) g_rowptr[n] = carry;
}

// ================= launch 3: qt GEMM | v GEMM + xb copy | CSR scatter =================
__global__ void __launch_bounds__(256) k_gemm2(
        const float* __restrict__ x,
        const float* __restrict__ Wv, const float* __restrict__ bv,
        int n, int e) {
    int m = blockIdx.y;
    if (m == 2) {
        // ---- CSR scatter (needs g_rowptr from k_scan) ----
        int total = gridDim.x * 256;
        for (int i = blockIdx.x * 256 + threadIdx.x; i < e; i += total) {
            int dst = g_edst[i];
            int pos = g_rowptr[dst] + atomicAdd(&g_cur[dst], 1);
            g_srcs[pos] = g_esrc[i];
        }
        return;
    }
    __shared__ float Xs[32][68];
    __shared__ float Ws[32][128];
    const float* W    = (m == 0) ? (const float*)g_M : Wv;
    const float* bias = (m == 0) ? (const float*)g_gvec : bv;

    int tx = threadIdx.x & 31;
    int ty = threadIdx.x >> 5;
    int row0 = blockIdx.x * 64;

    if (m == 1) {
        // ---- xb: bf16 copy of this block's 64 rows (x is L2-hot) ----
        for (int it = 0; it < 4; it++) {
            int idx = blockIdx.x * 1024 + threadIdx.x + it * 256;   // float4 index
            if (idx < n * 16) {
                float4 xv = ((const float4*)x)[idx];
                __nv_bfloat162 lo = __floats2bfloat162_rn(xv.x, xv.y);
                __nv_bfloat162 hi = __floats2bfloat162_rn(xv.z, xv.w);
                uint2 u;
                u.x = *(unsigned*)&lo;
                u.y = *(unsigned*)&hi;
                ((uint2*)g_xb)[idx] = u;
            }
        }
    }

    float acc[8][4];
#pragma unroll
    for (int i = 0; i < 8; i++)
#pragma unroll
        for (int j = 0; j < 4; j++) acc[i][j] = 0.f;

    for (int kc = 0; kc < 2; kc++) {
#pragma unroll
        for (int it = 0; it < 2; it++) {
            int idx = threadIdx.x + it * 256;
            int r = idx >> 3, kq = idx & 7;
            float4 xv = make_float4(0.f, 0.f, 0.f, 0.f);
            if (row0 + r < n) xv = ((const float4*)x)[(size_t)(row0 + r) * 16 + kc * 8 + kq];
            Xs[kq * 4 + 0][r] = xv.x;
            Xs[kq * 4 + 1][r] = xv.y;
            Xs[kq * 4 + 2][r] = xv.z;
            Xs[kq * 4 + 3][r] = xv.w;
        }
#pragma unroll
        for (int it = 0; it < 4; it++) {
            int idx = threadIdx.x + it * 256;
            ((float4*)Ws)[idx] = ((const float4*)W)[kc * 1024 + idx];
        }
        __syncthreads();
#pragma unroll
        for (int k = 0; k < 32; k++) {
            float4 a0 = *(const float4*)&Xs[k][ty * 8];
            float4 a1 = *(const float4*)&Xs[k][ty * 8 + 4];
            float4 b  = *(const float4*)&Ws[k][tx * 4];
            float af[8] = {a0.x, a0.y, a0.z, a0.w, a1.x, a1.y, a1.z, a1.w};
#pragma unroll
            for (int i = 0; i < 8; i++) {
                acc[i][0] = fmaf(af[i], b.x, acc[i][0]);
                acc[i][1] = fmaf(af[i], b.y, acc[i][1]);
                acc[i][2] = fmaf(af[i], b.z, acc[i][2]);
                acc[i][3] = fmaf(af[i], b.w, acc[i][3]);
            }
        }
        __syncthreads();
    }
    float4 bv4 = *(const float4*)&bias[tx * 4];
    if (m == 0) {
#pragma unroll
        for (int i = 0; i < 8; i++) {
            int r = row0 + ty * 8 + i;
            if (r < n)
                *(float4*)&g_qt[(size_t)r * 128 + tx * 4] =
                    make_float4(acc[i][0] + bv4.x, acc[i][1] + bv4.y,
                                acc[i][2] + bv4.z, acc[i][3] + bv4.w);
        }
    } else {
#pragma unroll
        for (int i = 0; i < 8; i++) {
            int r = row0 + ty * 8 + i;
            if (r < n) {
                __nv_bfloat162 lo = __floats2bfloat162_rn(acc[i][0] + bv4.x, acc[i][1] + bv4.y);
                __nv_bfloat162 hi = __floats2bfloat162_rn(acc[i][2] + bv4.z, acc[i][3] + bv4.w);
                uint2 u;
                u.x = *(unsigned*)&lo;
                u.y = *(unsigned*)&hi;
                *(uint2*)&g_v[(size_t)r * 128 + tx * 4] = u;
            }
        }
    }
}

// ================= launch 4: attention (R9 best version) =================
__device__ __forceinline__ float2 bf2f(unsigned u) {
    return __bfloat1622float2(*(__nv_bfloat162*)&u);
}

__global__ void __launch_bounds__(256) k_attn(int n) {
    int node = blockIdx.x * 8 + (threadIdx.x >> 5);
    if (node >= n) return;
    int lane = threadIdx.x & 31;
    int l15 = lane & 15;

    float4 qt = *(const float4*)&g_qt[(size_t)node * 128 + lane * 4];
    int beg = g_rowptr[node], end = g_rowptr[node + 1];

    const uint2* xb = (const uint2*)g_xb;
    const uint2* vb = (const uint2*)g_v;

    float denom = 0.f;
    float4 acc = make_float4(0.f, 0.f, 0.f, 0.f);

    int t = beg;
    for (; t + 4 <= end; t += 4) {
        int s0 = g_srcs[t + 0], s1 = g_srcs[t + 1], s2 = g_srcs[t + 2], s3 = g_srcs[t + 3];
        uint2 X0 = xb[(size_t)s0 * 16 + l15];
        uint2 X1 = xb[(size_t)s1 * 16 + l15];
        uint2 X2 = xb[(size_t)s2 * 16 + l15];
        uint2 X3 = xb[(size_t)s3 * 16 + l15];
        uint2 V0 = vb[(size_t)s0 * 32 + lane];
        uint2 V1 = vb[(size_t)s1 * 32 + lane];
        uint2 V2 = vb[(size_t)s2 * 32 + lane];
        uint2 V3 = vb[(size_t)s3 * 32 + lane];

        float2 a, b;
        a = bf2f(X0.x); b = bf2f(X0.y);
        float d0 = qt.x * a.x + qt.y * a.y + qt.z * b.x + qt.w * b.y;
        a = bf2f(X1.x); b = bf2f(X1.y);
        float d1 = qt.x * a.x + qt.y * a.y + qt.z * b.x + qt.w * b.y;
        a = bf2f(X2.x); b = bf2f(X2.y);
        float d2 = qt.x * a.x + qt.y * a.y + qt.z * b.x + qt.w * b.y;
        a = bf2f(X3.x); b = bf2f(X3.y);
        float d3 = qt.x * a.x + qt.y * a.y + qt.z * b.x + qt.w * b.y;
#pragma unroll
        for (int off = 8; off > 0; off >>= 1) {
            d0 += __shfl_xor_sync(0xffffffffu, d0, off);
            d1 += __shfl_xor_sync(0xffffffffu, d1, off);
            d2 += __shfl_xor_sync(0xffffffffu, d2, off);
            d3 += __shfl_xor_sync(0xffffffffu, d3, off);
        }
        float w0 = __expf(d0 * 0.125f);
        float w1 = __expf(d1 * 0.125f);
        float w2 = __expf(d2 * 0.125f);
        float w3 = __expf(d3 * 0.125f);
        denom += (w0 + w1) + (w2 + w3);

        a = bf2f(V0.x); b = bf2f(V0.y);
        acc.x = fmaf(w0, a.x, acc.x); acc.y = fmaf(w0, a.y, acc.y);
        acc.z = fmaf(w0, b.x, acc.z); acc.w = fmaf(w0, b.y, acc.w);
        a = bf2f(V1.x); b = bf2f(V1.y);
        acc.x = fmaf(w1, a.x, acc.x); acc.y = fmaf(w1, a.y, acc.y);
        acc.z = fmaf(w1, b.x, acc.z); acc.w = fmaf(w1, b.y, acc.w);
        a = bf2f(V2.x); b = bf2f(V2.y);
        acc.x = fmaf(w2, a.x, acc.x); acc.y = fmaf(w2, a.y, acc.y);
        acc.z = fmaf(w2, b.x, acc.z); acc.w = fmaf(w2, b.y, acc.w);
        a = bf2f(V3.x); b = bf2f(V3.y);
        acc.x = fmaf(w3, a.x, acc.x); acc.y = fmaf(w3, a.y, acc.y);
        acc.z = fmaf(w3, b.x, acc.z); acc.w = fmaf(w3, b.y, acc.w);
    }
    for (; t < end; t++) {
        int s = g_srcs[t];
        uint2 X = xb[(size_t)s * 16 + l15];
        uint2 V = vb[(size_t)s * 32 + lane];
        float2 a = bf2f(X.x);
        float2 b = bf2f(X.y);
        float d = qt.x * a.x + qt.y * a.y + qt.z * b.x + qt.w * b.y;
#pragma unroll
        for (int off = 8; off > 0; off >>= 1) d += __shfl_xor_sync(0xffffffffu, d, off);
        float w = __expf(d * 0.125f);
        denom += w;
        a = bf2f(V.x); b = bf2f(V.y);
        acc.x = fmaf(w, a.x, acc.x); acc.y = fmaf(w, a.y, acc.y);
        acc.z = fmaf(w, b.x, acc.z); acc.w = fmaf(w, b.y, acc.w);
    }
    float inv = 1.f / (denom + 1e-16f);
    acc.x *= inv; acc.y *= inv; acc.z *= inv; acc.w *= inv;
    ((float4*)g_agg)[(size_t)node * 32 + lane] = acc;
}

// ================= launch 5: out = agg@Wc + x@W2 + b2, fused LN stats =================
__global__ void __launch_bounds__(256) k_final(const float* __restrict__ x,
                                               const float* __restrict__ Wc,
                                               float* __restrict__ out, int n) {
    __shared__ float Xs[32][132];
    __shared__ float Ws[32][64];
    __shared__ float rs[8], rss[8];

    int tx = threadIdx.x & 15;
    int ty = threadIdx.x >> 4;
    int row0 = blockIdx.x * 128;

    float acc[8][4];
#pragma unroll
    for (int i = 0; i < 8; i++)
#pragma unroll
        for (int j = 0; j < 4; j++) acc[i][j] = 0.f;

    for (int kc = 0; kc < 6; kc++) {
#pragma unroll
        for (int it = 0; it < 4; it++) {
            int idx = threadIdx.x + it * 256;
            int r = idx >> 3, kq = idx & 7;
            float4 av = make_float4(0.f, 0.f, 0.f, 0.f);
            if (row0 + r < n) {
                if (kc < 4) av = ((const float4*)g_agg)[(size_t)(row0 + r) * 32 + kc * 8 + kq];
                else        av = ((const float4*)x)[(size_t)(row0 + r) * 16 + (kc - 4) * 8 + kq];
            }
            Xs[kq * 4 + 0][r] = av.x;
            Xs[kq * 4 + 1][r] = av.y;
            Xs[kq * 4 + 2][r] = av.z;
            Xs[kq * 4 + 3][r] = av.w;
        }
#pragma unroll
        for (int it = 0; it < 2; it++) {
            int idx = threadIdx.x + it * 256;
            int k = idx >> 4, c4 = idx & 15;
            float4 wv;
            if (kc < 4) wv = ((const float4*)Wc)[(kc * 32 + k) * 16 + c4];
            else        wv = ((const float4*)g_W2)[((kc - 4) * 32 + k) * 16 + c4];
            *(float4*)&Ws[k][c4 * 4] = wv;
        }
        __syncthreads();
#pragma unroll
        for (int k = 0; k < 32; k++) {
            float4 a0 = *(const float4*)&Xs[k][ty * 8];
            float4 a1 = *(const float4*)&Xs[k][ty * 8 + 4];
            float4 b  = *(const float4*)&Ws[k][tx * 4];
            float af[8] = {a0.x, a0.y, a0.z, a0.w, a1.x, a1.y, a1.z, a1.w};
#pragma unroll
            for (int i = 0; i < 8; i++) {
                acc[i][0] = fmaf(af[i], b.x, acc[i][0]);
                acc[i][1] = fmaf(af[i], b.y, acc[i][1]);
                acc[i][2] = fmaf(af[i], b.z, acc[i][2]);
                acc[i][3] = fmaf(af[i], b.w, acc[i][3]);
            }
        }
        __syncthreads();
    }

    float4 b2 = *(const float4*)&g_b2[tx * 4];
    float s = 0.f, ss = 0.f;
#pragma unroll
    for (int i = 0; i < 8; i++) {
        int r = row0 + ty * 8 + i;
        if (r < n) {
            float4 o = make_float4(acc[i][0] + b2.x, acc[i][1] + b2.y,
                                   acc[i][2] + b2.z, acc[i][3] + b2.w);
            *(float4*)&out[(size_t)r * 64 + tx * 4] = o;
            s += (o.x + o.y) + (o.z + o.w);
            ss += o.x * o.x + o.y * o.y + o.z * o.z + o.w * o.w;
        }
    }
#pragma unroll
    for (int off = 16; off > 0; off >>= 1) {
        s  += __shfl_xor_sync(0xffffffffu, s, off);
        ss += __shfl_xor_sync(0xffffffffu, ss, off);
    }
    int wid = threadIdx.x >> 5, lane = threadIdx.x & 31;
    if (lane == 0) { rs[wid] = s; rss[wid] = ss; }
    __syncthreads();
    if (threadIdx.x == 0) {
        double S = 0.0, SS = 0.0;
        for (int w = 0; w < 8; w++) { S += (double)rs[w]; SS += (double)rss[w]; }
        atomicAdd(&g_stats[0], S);
        atomicAdd(&g_stats[1], SS);
    }
}

// ================= launch 6: graph-level LayerNorm + zero cnt/cur for next call =================
__global__ void k_norm(float* __restrict__ out, const float* __restrict__ gamma,
                       const float* __restrict__ beta, int total, int n) {
    int i = blockIdx.x * blockDim.x + threadIdx.x;
    if (i < n) { g_cnt[i] = 0; g_cur[i] = 0; }   // prep next call (deterministic every call)
    if (i < total) {
        double M = (double)total;
        double mean = g_stats[0] / M;
        double var  = g_stats[1] / M - mean * mean;
        if (var < 0.0) var = 0.0;
        float stdv = (float)sqrt(var);
        float v = out[i];
        int d = i & 63;
        out[i] = (v - (float)mean) / (stdv + 1e-5f) * __ldg(&gamma[d]) + __ldg(&beta[d]);
    }
}

// ---------------- launch ----------------
extern "C" void kernel_launch(void* const* d_in, const int* in_sizes, int n_in,
                              void* d_out, int out_size) {
    const float* x    = (const float*)d_in[0];
    const void*  ei   = d_in[1];
    const float* Wq   = (const float*)d_in[2];
    const float* bq   = (const float*)d_in[3];
    const float* Wk   = (const float*)d_in[4];
    const float* Wv   = (const float*)d_in[6];
    const float* bv   = (const float*)d_in[7];
    const float* Wsk  = (const float*)d_in[8];
    const float* bsk  = (const float*)d_in[9];
    const float* Wc   = (const float*)d_in[10];
    const float* bc   = (const float*)d_in[11];
    const float* gam  = (const float*)d_in[12];
    const float* bet  = (const float*)d_in[13];
    float* out = (float*)d_out;

    int n = in_sizes[0] / 64;
    int e = in_sizes[1] / 2;

    int nconv = (2 * e + 255) / 256;
    k_cvprep<<<nconv + 390, 256>>>(ei, e, Wq, bq, Wk, Wsk, bsk, Wc, bc);  // #1
    k_scan<<<1, 1024>>>(n);                                               // #2
    k_gemm2<<<dim3((n + 63) / 64, 3), 256>>>(x, Wv, bv, n, e);            // #3
    k_attn<<<(n + 7) / 8, 256>>>(n);                                      // #4  <- capture slot
    k_final<<<(n + 127) / 128, 256>>>(x, Wc, out, n);                     // #5
    k_norm<<<(n * 64 + 255) / 256, 256>>>(out, gam, bet, n * 64, n);      // #6
}

// round 12
// speedup vs baseline: 1.0044x; 1.0044x over previous
#include <cuda_runtime.h>
#include <cuda_bf16.h>
#include <math.h>

#define MAXN 50000
#define MAXE 800000

// ---------------- device scratch ----------------
__device__ __align__(16) float g_qt [(size_t)MAXN * 128];  // x@(WqWk^T) + gvec
// interleaved per-node record: 48 uint2 = 384B: [0:16)=x bf16 (64), [16:48)=v bf16 (128)
__device__ __align__(128) __nv_bfloat16 g_xv[(size_t)MAXN * 192];
__device__ __align__(16) float g_agg[(size_t)MAXN * 128];   // attention output
__device__ __align__(16) float g_M  [64 * 128];             // Mcat = Wq Wk^T per head
__device__ __align__(16) float g_W2 [64 * 64];              // Wskip @ Wc
__device__ float  g_gvec[128];                               // Wk_h @ bq_h per head
__device__ float  g_b2[64];                                  // bskip@Wc + bc
__device__ int    g_esrc [MAXE];
__device__ int    g_edst [MAXE];
__device__ int    g_srcs [MAXE];   // PRE-SCALED: src*48 (uint2 offset of node record)
__device__ int    g_cnt  [MAXN];
__device__ int    g_cur  [MAXN];
__device__ int    g_rowptr[MAXN + 1];
__device__ double g_stats[2];

// ================= 1: init =================
__global__ void k_init(int n) {
    int i = blockIdx.x * blockDim.x + threadIdx.x;
    if (i < n) { g_cnt[i] = 0; g_cur[i] = 0; }
    if (i == 0) { g_stats[0] = 0.0; g_stats[1] = 0.0; }
}

// ================= 2: convert (self-detecting dtype) + fused dst histogram =================
__global__ void k_convert(const void* __restrict__ ei, int e) {
    __shared__ int s_is64;
    if (threadIdx.x == 0) {
        const int* w = (const int*)ei;
        int all0 = 1;
        for (int i = 1; i < 64; i += 2) all0 &= (w[i] == 0);
        s_is64 = all0;
    }
    __syncthreads();
    int i = blockIdx.x * blockDim.x + threadIdx.x;
    if (i >= 2 * e) return;
    int v;
    if (s_is64) v = (int)((const long long*)ei)[i];
    else        v = ((const int*)ei)[i];
    if (i < e) g_esrc[i] = v;
    else { g_edst[i - e] = v; atomicAdd(&g_cnt[v], 1); }
}

// ================= 3: single-block exclusive scan =================
__global__ void __launch_bounds__(1024) k_scan(int n) {
    __shared__ int warpsum[32];
    int tid = threadIdx.x;
    int lane = tid & 31, wid = tid >> 5;
    int carry = 0;
    int nchunk = (n + 1023) >> 10;
    for (int c = 0; c < nchunk; c++) {
        int i = (c << 10) + tid;
        int v = (i < n) ? g_cnt[i] : 0;
        int s = v;
#pragma unroll
        for (int off = 1; off < 32; off <<= 1) {
            int t = __shfl_up_sync(0xffffffffu, s, off);
            if (lane >= off) s += t;
        }
        if (lane == 31) warpsum[wid] = s;
        __syncthreads();
        if (wid == 0) {
            int ws = warpsum[lane];
#pragma unroll
            for (int off = 1; off < 32; off <<= 1) {
                int t = __shfl_up_sync(0xffffffffu, ws, off);
                if (lane >= off) ws += t;
            }
            warpsum[lane] = ws;
        }
        __syncthreads();
        int base = (wid > 0) ? warpsum[wid - 1] : 0;
        if (i < n) g_rowptr[i] = carry + base + s - v;
        carry += warpsum[31];
        __syncthreads();
    }
    if (tid == 0) g_rowptr[n] = carry;
}

// ================= 4: CSR scatter (PROFILED SLOT) =================
__global__ void k_scatter(int e) {
    int i = blockIdx.x * blockDim.x + threadIdx.x;
    if (i < e) {
        int dst = g_edst[i];
        int pos = g_rowptr[dst] + atomicAdd(&g_cur[dst], 1);
        g_srcs[pos] = g_esrc[i] * 48;   // pre-scaled uint2 offset of node record
    }
}

// ================= 5: precomputes =================
__global__ void k_prep(const float* __restrict__ Wq, const float* __restrict__ bq,
                       const float* __restrict__ Wk,
                       const float* __restrict__ Wsk, const float* __restrict__ bsk,
                       const float* __restrict__ Wc, const float* __restrict__ bc) {
    int idx = blockIdx.x * 256 + threadIdx.x;
    int g = idx >> 3, part = idx & 7;
    float s = 0.f;
    int valid = 0;
    float* dst = 0;
    if (g < 8192) {                      // Mcat
        int i = g >> 7, col = g & 127, h = col >> 6, j = col & 63;
        const float* wq = Wq + i * 128 + h * 64 + part * 8;
        const float* wk = Wk + j * 128 + h * 64 + part * 8;
#pragma unroll
        for (int c = 0; c < 8; c++) s = fmaf(wq[c], wk[c], s);
        dst = &g_M[g]; valid = 1;
    } else if (g < 12288) {              // W2
        int o = g - 8192, r = o >> 6, c = o & 63;
#pragma unroll
        for (int k = 0; k < 16; k++)
            s = fmaf(Wsk[r * 128 + part * 16 + k], Wc[(part * 16 + k) * 64 + c], s);
        dst = &g_W2[o]; valid = 1;
    } else if (g < 12352) {              // b2
        int c = g - 12288;
        if (part == 0) s = bc[c];
#pragma unroll
        for (int k = 0; k < 16; k++)
            s = fmaf(bsk[part * 16 + k], Wc[(part * 16 + k) * 64 + c], s);
        dst = &g_b2[c]; valid = 1;
    } else if (g < 12480) {              // gvec
        int o = g - 12352, h = o >> 6, i = o & 63;
#pragma unroll
        for (int j = 0; j < 8; j++)
            s = fmaf(Wk[i * 128 + h * 64 + part * 8 + j], bq[h * 64 + part * 8 + j], s);
        dst = &g_gvec[o]; valid = 1;
    }
    s += __shfl_xor_sync(0xffffffffu, s, 1);
    s += __shfl_xor_sync(0xffffffffu, s, 2);
    s += __shfl_xor_sync(0xffffffffu, s, 4);
    if (valid && part == 0) *dst = s;
}

// ================= 6: x -> bf16 into interleaved record (slots 0..15) =================
__global__ void k_xb(const float* __restrict__ x, int n) {
    int i = blockIdx.x * 256 + threadIdx.x;
    if (i < n * 16) {
        int node = i >> 4, slot = i & 15;
        float4 xv = ((const float4*)x)[i];
        __nv_bfloat162 lo = __floats2bfloat162_rn(xv.x, xv.y);
        __nv_bfloat162 hi = __floats2bfloat162_rn(xv.z, xv.w);
        uint2 u;
        u.x = *(unsigned*)&lo;
        u.y = *(unsigned*)&hi;
        ((uint2*)g_xv)[(size_t)node * 48 + slot] = u;
    }
}

// ================= 7: qt = x@Mcat + gvec (fp32) | v = x@Wv+bv (bf16, slots 16..47) =================
__global__ void __launch_bounds__(256) k_gemm2(
        const float* __restrict__ x,
        const float* __restrict__ Wv, const float* __restrict__ bv,
        int n) {
    __shared__ float Xs[32][68];
    __shared__ float Ws[32][128];
    int m = blockIdx.y;
    const float* W    = (m == 0) ? (const float*)g_M : Wv;
    const float* bias = (m == 0) ? (const float*)g_gvec : bv;

    int tx = threadIdx.x & 31;
    int ty = threadIdx.x >> 5;
    int row0 = blockIdx.x * 64;

    float acc[8][4];
#pragma unroll
    for (int i = 0; i < 8; i++)
#pragma unroll
        for (int j = 0; j < 4; j++) acc[i][j] = 0.f;

    for (int kc = 0; kc < 2; kc++) {
#pragma unroll
        for (int it = 0; it < 2; it++) {
            int idx = threadIdx.x + it * 256;
            int r = idx >> 3, kq = idx & 7;
            float4 xv = make_float4(0.f, 0.f, 0.f, 0.f);
            if (row0 + r < n) xv = ((const float4*)x)[(size_t)(row0 + r) * 16 + kc * 8 + kq];
            Xs[kq * 4 + 0][r] = xv.x;
            Xs[kq * 4 + 1][r] = xv.y;
            Xs[kq * 4 + 2][r] = xv.z;
            Xs[kq * 4 + 3][r] = xv.w;
        }
#pragma unroll
        for (int it = 0; it < 4; it++) {
            int idx = threadIdx.x + it * 256;
            ((float4*)Ws)[idx] = ((const float4*)W)[kc * 1024 + idx];
        }
        __syncthreads();
#pragma unroll
        for (int k = 0; k < 32; k++) {
            float4 a0 = *(const float4*)&Xs[k][ty * 8];
            float4 a1 = *(const float4*)&Xs[k][ty * 8 + 4];
            float4 b  = *(const float4*)&Ws[k][tx * 4];
            float af[8] = {a0.x, a0.y, a0.z, a0.w, a1.x, a1.y, a1.z, a1.w};
#pragma unroll
            for (int i = 0; i < 8; i++) {
                acc[i][0] = fmaf(af[i], b.x, acc[i][0]);
                acc[i][1] = fmaf(af[i], b.y, acc[i][1]);
                acc[i][2] = fmaf(af[i], b.z, acc[i][2]);
                acc[i][3] = fmaf(af[i], b.w, acc[i][3]);
            }
        }
        __syncthreads();
    }
    float4 bv4 = *(const float4*)&bias[tx * 4];
    if (m == 0) {
#pragma unroll
        for (int i = 0; i < 8; i++) {
            int r = row0 + ty * 8 + i;
            if (r < n)
                *(float4*)&g_qt[(size_t)r * 128 + tx * 4] =
                    make_float4(acc[i][0] + bv4.x, acc[i][1] + bv4.y,
                                acc[i][2] + bv4.z, acc[i][3] + bv4.w);
        }
    } else {
#pragma unroll
        for (int i = 0; i < 8; i++) {
            int r = row0 + ty * 8 + i;
            if (r < n) {
                __nv_bfloat162 lo = __floats2bfloat162_rn(acc[i][0] + bv4.x, acc[i][1] + bv4.y);
                __nv_bfloat162 hi = __floats2bfloat162_rn(acc[i][2] + bv4.z, acc[i][3] + bv4.w);
                uint2 u;
                u.x = *(unsigned*)&lo;
                u.y = *(unsigned*)&hi;
                ((uint2*)g_xv)[(size_t)r * 48 + 16 + tx] = u;
            }
        }
    }
}

// ================= 8: attention =================
__device__ __forceinline__ float2 bf2f(unsigned u) {
    return __bfloat1622float2(*(__nv_bfloat162*)&u);
}

__global__ void __launch_bounds__(256) k_attn(int n) {
    int node = blockIdx.x * 8 + (threadIdx.x >> 5);
    if (node >= n) return;
    int lane = threadIdx.x & 31;
    int l15 = lane & 15;

    float4 qt = *(const float4*)&g_qt[(size_t)node * 128 + lane * 4];
    int beg = g_rowptr[node], end = g_rowptr[node + 1];

    // loop-invariant lane pointers; g_srcs holds pre-scaled record offsets
    const uint2* xp = (const uint2*)g_xv + l15;
    const uint2* vp = (const uint2*)g_xv + 16 + lane;

    float denom = 0.f;
    float4 acc = make_float4(0.f, 0.f, 0.f, 0.f);

    int t = beg;
    for (; t + 4 <= end; t += 4) {
        int o0 = g_srcs[t + 0], o1 = g_srcs[t + 1], o2 = g_srcs[t + 2], o3 = g_srcs[t + 3];
        uint2 X0 = xp[o0], X1 = xp[o1], X2 = xp[o2], X3 = xp[o3];
        uint2 V0 = vp[o0], V1 = vp[o1], V2 = vp[o2], V3 = vp[o3];

        float2 a, b;
        a = bf2f(X0.x); b = bf2f(X0.y);
        float d0 = qt.x * a.x + qt.y * a.y + qt.z * b.x + qt.w * b.y;
        a = bf2f(X1.x); b = bf2f(X1.y);
        float d1 = qt.x * a.x + qt.y * a.y + qt.z * b.x + qt.w * b.y;
        a = bf2f(X2.x); b = bf2f(X2.y);
        float d2 = qt.x * a.x + qt.y * a.y + qt.z * b.x + qt.w * b.y;
        a = bf2f(X3.x); b = bf2f(X3.y);
        float d3 = qt.x * a.x + qt.y * a.y + qt.z * b.x + qt.w * b.y;
#pragma unroll
        for (int off = 8; off > 0; off >>= 1) {
            d0 += __shfl_xor_sync(0xffffffffu, d0, off);
            d1 += __shfl_xor_sync(0xffffffffu, d1, off);
            d2 += __shfl_xor_sync(0xffffffffu, d2, off);
            d3 += __shfl_xor_sync(0xffffffffu, d3, off);
        }
        float w0 = __expf(d0 * 0.125f);
        float w1 = __expf(d1 * 0.125f);
        float w2 = __expf(d2 * 0.125f);
        float w3 = __expf(d3 * 0.125f);
        denom += (w0 + w1) + (w2 + w3);

        a = bf2f(V0.x); b = bf2f(V0.y);
        acc.x = fmaf(w0, a.x, acc.x); acc.y = fmaf(w0, a.y, acc.y);
        acc.z = fmaf(w0, b.x, acc.z); acc.w = fmaf(w0, b.y, acc.w);
        a = bf2f(V1.x); b = bf2f(V1.y);
        acc.x = fmaf(w1, a.x, acc.x); acc.y = fmaf(w1, a.y, acc.y);
        acc.z = fmaf(w1, b.x, acc.z); acc.w = fmaf(w1, b.y, acc.w);
        a = bf2f(V2.x); b = bf2f(V2.y);
        acc.x = fmaf(w2, a.x, acc.x); acc.y = fmaf(w2, a.y, acc.y);
        acc.z = fmaf(w2, b.x, acc.z); acc.w = fmaf(w2, b.y, acc.w);
        a = bf2f(V3.x); b = bf2f(V3.y);
        acc.x = fmaf(w3, a.x, acc.x); acc.y = fmaf(w3, a.y, acc.y);
        acc.z = fmaf(w3, b.x, acc.z); acc.w = fmaf(w3, b.y, acc.w);
    }
    for (; t < end; t++) {
        int o = g_srcs[t];
        uint2 X = xp[o];
        uint2 V = vp[o];
        float2 a = bf2f(X.x);
        float2 b = bf2f(X.y);
        float d = qt.x * a.x + qt.y * a.y + qt.z * b.x + qt.w * b.y;
#pragma unroll
        for (int off = 8; off > 0; off >>= 1) d += __shfl_xor_sync(0xffffffffu, d, off);
        float w = __expf(d * 0.125f);
        denom += w;
        a = bf2f(V.x); b = bf2f(V.y);
        acc.x = fmaf(w, a.x, acc.x); acc.y = fmaf(w, a.y, acc.y);
        acc.z = fmaf(w, b.x, acc.z); acc.w = fmaf(w, b.y, acc.w);
    }
    float inv = 1.f / (denom + 1e-16f);
    acc.x *= inv; acc.y *= inv; acc.z *= inv; acc.w *= inv;
    ((float4*)g_agg)[(size_t)node * 32 + lane] = acc;
}

// ================= 9: out = agg@Wc + x@W2 + b2, fused LN stats =================
__global__ void __launch_bounds__(256) k_final(const float* __restrict__ x,
                                               const float* __restrict__ Wc,
                                               float* __restrict__ out, int n) {
    __shared__ float Xs[32][132];
    __shared__ float Ws[32][64];
    __shared__ float rs[8], rss[8];

    int tx = threadIdx.x & 15;
    int ty = threadIdx.x >> 4;
    int row0 = blockIdx.x * 128;

    float acc[8][4];
#pragma unroll
    for (int i = 0; i < 8; i++)
#pragma unroll
        for (int j = 0; j < 4; j++) acc[i][j] = 0.f;

    for (int kc = 0; kc < 6; kc++) {
#pragma unroll
        for (int it = 0; it < 4; it++) {
            int idx = threadIdx.x + it * 256;
            int r = idx >> 3, kq = idx & 7;
            float4 av = make_float4(0.f, 0.f, 0.f, 0.f);
            if (row0 + r < n) {
                if (kc < 4) av = ((const float4*)g_agg)[(size_t)(row0 + r) * 32 + kc * 8 + kq];
                else        av = ((const float4*)x)[(size_t)(row0 + r) * 16 + (kc - 4) * 8 + kq];
            }
            Xs[kq * 4 + 0][r] = av.x;
            Xs[kq * 4 + 1][r] = av.y;
            Xs[kq * 4 + 2][r] = av.z;
            Xs[kq * 4 + 3][r] = av.w;
        }
#pragma unroll
        for (int it = 0; it < 2; it++) {
            int idx = threadIdx.x + it * 256;
            int k = idx >> 4, c4 = idx & 15;
            float4 wv;
            if (kc < 4) wv = ((const float4*)Wc)[(kc * 32 + k) * 16 + c4];
            else        wv = ((const float4*)g_W2)[((kc - 4) * 32 + k) * 16 + c4];
            *(float4*)&Ws[k][c4 * 4] = wv;
        }
        __syncthreads();
#pragma unroll
        for (int k = 0; k < 32; k++) {
            float4 a0 = *(const float4*)&Xs[k][ty * 8];
            float4 a1 = *(const float4*)&Xs[k][ty * 8 + 4];
            float4 b  = *(const float4*)&Ws[k][tx * 4];
            float af[8] = {a0.x, a0.y, a0.z, a0.w, a1.x, a1.y, a1.z, a1.w};
#pragma unroll
            for (int i = 0; i < 8; i++) {
                acc[i][0] = fmaf(af[i], b.x, acc[i][0]);
                acc[i][1] = fmaf(af[i], b.y, acc[i][1]);
                acc[i][2] = fmaf(af[i], b.z, acc[i][2]);
                acc[i][3] = fmaf(af[i], b.w, acc[i][3]);
            }
        }
        __syncthreads();
    }

    float4 b2 = *(const float4*)&g_b2[tx * 4];
    float s = 0.f, ss = 0.f;
#pragma unroll
    for (int i = 0; i < 8; i++) {
        int r = row0 + ty * 8 + i;
        if (r < n) {
            float4 o = make_float4(acc[i][0] + b2.x, acc[i][1] + b2.y,
                                   acc[i][2] + b2.z, acc[i][3] + b2.w);
            *(float4*)&out[(size_t)r * 64 + tx * 4] = o;
            s += (o.x + o.y) + (o.z + o.w);
            ss += o.x * o.x + o.y * o.y + o.z * o.z + o.w * o.w;
        }
    }
#pragma unroll
    for (int off = 16; off > 0; off >>= 1) {
        s  += __shfl_xor_sync(0xffffffffu, s, off);
        ss += __shfl_xor_sync(0xffffffffu, ss, off);
    }
    int wid = threadIdx.x >> 5, lane = threadIdx.x & 31;
    if (lane == 0) { rs[wid] = s; rss[wid] = ss; }
    __syncthreads();
    if (threadIdx.x == 0) {
        double S = 0.0, SS = 0.0;
        for (int w = 0; w < 8; w++) { S += (double)rs[w]; SS += (double)rss[w]; }
        atomicAdd(&g_stats[0], S);
        atomicAdd(&g_stats[1], SS);
    }
}

// ================= 10: graph-level LayerNorm =================
__global__ void k_norm(float* __restrict__ out, const float* __restrict__ gamma,
                       const float* __restrict__ beta, int total) {
    int i = blockIdx.x * blockDim.x + threadIdx.x;
    if (i < total) {
        double M = (double)total;
        double mean = g_stats[0] / M;
        double var  = g_stats[1] / M - mean * mean;
        if (var < 0.0) var = 0.0;
        float stdv = (float)sqrt(var);
        float v = out[i];
        int d = i & 63;
        out[i] = (v - (float)mean) / (stdv + 1e-5f) * __ldg(&gamma[d]) + __ldg(&beta[d]);
    }
}

// ---------------- launch ----------------
extern "C" void kernel_launch(void* const* d_in, const int* in_sizes, int n_in,
                              void* d_out, int out_size) {
    const float* x    = (const float*)d_in[0];
    const void*  ei   = d_in[1];
    const float* Wq   = (const float*)d_in[2];
    const float* bq   = (const float*)d_in[3];
    const float* Wk   = (const float*)d_in[4];
    const float* Wv   = (const float*)d_in[6];
    const float* bv   = (const float*)d_in[7];
    const float* Wsk  = (const float*)d_in[8];
    const float* bsk  = (const float*)d_in[9];
    const float* Wc   = (const float*)d_in[10];
    const float* bc   = (const float*)d_in[11];
    const float* gam  = (const float*)d_in[12];
    const float* bet  = (const float*)d_in[13];
    float* out = (float*)d_out;

    int n = in_sizes[0] / 64;
    int e = in_sizes[1] / 2;

    k_init<<<(n + 255) / 256, 256>>>(n);                                  // #1
    k_convert<<<(2 * e + 255) / 256, 256>>>(ei, e);                       // #2
    k_scan<<<1, 1024>>>(n);                                               // #3
    k_scatter<<<(e + 255) / 256, 256>>>(e);                               // #4 <- capture slot
    k_prep<<<390, 256>>>(Wq, bq, Wk, Wsk, bsk, Wc, bc);                   // #5
    k_xb<<<(n * 16 + 255) / 256, 256>>>(x, n);                            // #6
    k_gemm2<<<dim3((n + 63) / 64, 2), 256>>>(x, Wv, bv, n);               // #7
    k_attn<<<(n + 7) / 8, 256>>>(n);                                      // #8
    k_final<<<(n + 127) / 128, 256>>>(x, Wc, out, n);                     // #9
    k_norm<<<(n * 64 + 255) / 256, 256>>>(out, gam, bet, n * 64);         // #10
}

// round 13
// speedup vs baseline: 1.0680x; 1.0634x over previous
#include <cuda_runtime.h>
#include <cuda_bf16.h>
#include <math.h>

#define MAXN 50000
#define MAXE 800000

// ---------------- device scratch ----------------
__device__ __align__(16) float g_qt [(size_t)MAXN * 128];       // x@(WqWk^T) + gvec
__device__ __align__(16) __nv_bfloat16 g_xb[(size_t)MAXN * 64]; // x in bf16 (gather side)
__device__ __align__(16) __nv_bfloat16 g_v [(size_t)MAXN * 128];// projected v, bf16
__device__ __align__(16) float g_agg[(size_t)MAXN * 128];       // attention output
__device__ __align__(16) float g_M  [64 * 128];                 // Mcat = Wq Wk^T per head
__device__ __align__(16) float g_W2 [64 * 64];                  // Wskip @ Wc
__device__ float  g_gvec[128];                                   // Wk_h @ bq_h per head
__device__ float  g_b2[64];                                      // bskip@Wc + bc
__device__ int    g_esrc [MAXE];
__device__ int    g_edst [MAXE];
__device__ int    g_srcs [MAXE];
__device__ int    g_cnt  [MAXN];
__device__ int    g_cur  [MAXN];
__device__ int    g_rowptr[MAXN + 1];
__device__ int    g_blksum[64];
__device__ int    g_is64;
__device__ double g_stats[2];

// ---------------- packed fp32x2 helpers (Blackwell dual-MAC) ----------------
__device__ __forceinline__ void fma2(unsigned long long& acc, unsigned long long a,
                                     unsigned long long b) {
    asm("fma.rn.f32x2 %0, %1, %2, %3;" : "=l"(acc) : "l"(a), "l"(b), "l"(acc));
}
__device__ __forceinline__ unsigned long long pack2(float x, float y) {
    unsigned long long r;
    asm("mov.b64 %0, {%1, %2};" : "=l"(r) : "f"(x), "f"(y));
    return r;
}
__device__ __forceinline__ float2 unpack2(unsigned long long v) {
    float2 r;
    asm("mov.b64 {%0, %1}, %2;" : "=f"(r.x), "=f"(r.y) : "l"(v));
    return r;
}

// ================= 1: init =================
__global__ void k_init(int n) {
    int i = blockIdx.x * blockDim.x + threadIdx.x;
    if (i < n) { g_cnt[i] = 0; g_cur[i] = 0; }
    if (i == 0) { g_stats[0] = 0.0; g_stats[1] = 0.0; }
}

// ================= 2: edge dtype sniff =================
__global__ void k_detect(const void* __restrict__ ei) {
    if (threadIdx.x == 0 && blockIdx.x == 0) {
        const int* w = (const int*)ei;
        int all0 = 1;
        for (int i = 1; i < 64; i += 2) all0 &= (w[i] == 0);
        g_is64 = all0;
    }
}

// ================= 3: precomputes (4 threads/output + quad shuffle reduce) =================
__global__ void k_prep(const float* __restrict__ Wq, const float* __restrict__ bq,
                       const float* __restrict__ Wk,
                       const float* __restrict__ Wsk, const float* __restrict__ bsk,
                       const float* __restrict__ Wc, const float* __restrict__ bc) {
    int idx = blockIdx.x * 256 + threadIdx.x;
    int g = idx >> 2, part = idx & 3;
    float s = 0.f;
    int valid = 0;
    float* dst = 0;
    if (g < 8192) {                      // Mcat
        int i = g >> 7, col = g & 127, h = col >> 6, j = col & 63;
        const float* wq = Wq + i * 128 + h * 64 + part * 16;
        const float* wk = Wk + j * 128 + h * 64 + part * 16;
#pragma unroll
        for (int c = 0; c < 16; c++) s = fmaf(wq[c], wk[c], s);
        dst = &g_M[g]; valid = 1;
    } else if (g < 12288) {              // W2
        int o = g - 8192, r = o >> 6, c = o & 63;
#pragma unroll
        for (int k = 0; k < 32; k++)
            s = fmaf(Wsk[r * 128 + part * 32 + k], Wc[(part * 32 + k) * 64 + c], s);
        dst = &g_W2[o]; valid = 1;
    } else if (g < 12352) {              // b2
        int c = g - 12288;
        if (part == 0) s = bc[c];
#pragma unroll
        for (int k = 0; k < 32; k++)
            s = fmaf(bsk[part * 32 + k], Wc[(part * 32 + k) * 64 + c], s);
        dst = &g_b2[c]; valid = 1;
    } else if (g < 12480) {              // gvec
        int o = g - 12352, h = o >> 6, i = o & 63;
#pragma unroll
        for (int j = 0; j < 16; j++)
            s = fmaf(Wk[i * 128 + h * 64 + part * 16 + j], bq[h * 64 + part * 16 + j], s);
        dst = &g_gvec[o]; valid = 1;
    }
    s += __shfl_xor_sync(0xffffffffu, s, 1);
    s += __shfl_xor_sync(0xffffffffu, s, 2);
    if (valid && part == 0) *dst = s;
}

// ================= 4: convert + fused dst histogram (PROFILED SLOT) =================
__global__ void k_convert(const void* __restrict__ ei, int e) {
    int i = blockIdx.x * blockDim.x + threadIdx.x;
    if (i >= 2 * e) return;
    int v;
    if (g_is64) v = (int)((const long long*)ei)[i];
    else        v = ((const int*)ei)[i];
    if (i < e) g_esrc[i] = v;
    else { g_edst[i - e] = v; atomicAdd(&g_cnt[v], 1); }
}

// ================= 5: x -> bf16 copy =================
__global__ void k_xb(const float* __restrict__ x, int n) {
    int i = blockIdx.x * 256 + threadIdx.x;
    if (i < n * 16) {
        float4 xv = ((const float4*)x)[i];
        __nv_bfloat162 lo = __floats2bfloat162_rn(xv.x, xv.y);
        __nv_bfloat162 hi = __floats2bfloat162_rn(xv.z, xv.w);
        uint2 u;
        u.x = *(unsigned*)&lo;
        u.y = *(unsigned*)&hi;
        ((uint2*)g_xb)[i] = u;
    }
}

// ================= 6: qt = x@Mcat + gvec (fp32) | v = x@Wv+bv (bf16), f32x2 core =================
__global__ void __launch_bounds__(256) k_gemm2(
        const float* __restrict__ x,
        const float* __restrict__ Wv, const float* __restrict__ bv,
        int n) {
    __shared__ float Xs[32][68];
    __shared__ float Ws[32][128];
    int m = blockIdx.y;
    const float* W    = (m == 0) ? (const float*)g_M : Wv;
    const float* bias = (m == 0) ? (const float*)g_gvec : bv;

    int tx = threadIdx.x & 31;
    int ty = threadIdx.x >> 5;
    int row0 = blockIdx.x * 64;

    // acc2[p][j] = {row 2p, row 2p+1} for col j  (8 rows x 4 cols as 4x4 pairs)
    unsigned long long acc2[4][4];
#pragma unroll
    for (int p = 0; p < 4; p++)
#pragma unroll
        for (int j = 0; j < 4; j++) acc2[p][j] = 0ull;

    for (int kc = 0; kc < 2; kc++) {
#pragma unroll
        for (int it = 0; it < 2; it++) {
            int idx = threadIdx.x + it * 256;
            int r = idx >> 3, kq = idx & 7;
            float4 xv = make_float4(0.f, 0.f, 0.f, 0.f);
            if (row0 + r < n) xv = ((const float4*)x)[(size_t)(row0 + r) * 16 + kc * 8 + kq];
            Xs[kq * 4 + 0][r] = xv.x;
            Xs[kq * 4 + 1][r] = xv.y;
            Xs[kq * 4 + 2][r] = xv.z;
            Xs[kq * 4 + 3][r] = xv.w;
        }
#pragma unroll
        for (int it = 0; it < 4; it++) {
            int idx = threadIdx.x + it * 256;
            ((float4*)Ws)[idx] = ((const float4*)W)[kc * 1024 + idx];
        }
        __syncthreads();
#pragma unroll
        for (int k = 0; k < 32; k++) {
            float4 a0 = *(const float4*)&Xs[k][ty * 8];       // warp-broadcast
            float4 a1 = *(const float4*)&Xs[k][ty * 8 + 4];
            float4 b  = *(const float4*)&Ws[k][tx * 4];       // coalesced
            unsigned long long A[4] = {pack2(a0.x, a0.y), pack2(a0.z, a0.w),
                                       pack2(a1.x, a1.y), pack2(a1.z, a1.w)};
            unsigned long long B[4] = {pack2(b.x, b.x), pack2(b.y, b.y),
                                       pack2(b.z, b.z), pack2(b.w, b.w)};
#pragma unroll
            for (int p = 0; p < 4; p++) {
                fma2(acc2[p][0], A[p], B[0]);
                fma2(acc2[p][1], A[p], B[1]);
                fma2(acc2[p][2], A[p], B[2]);
                fma2(acc2[p][3], A[p], B[3]);
            }
        }
        __syncthreads();
    }
    float4 bv4 = *(const float4*)&bias[tx * 4];
#pragma unroll
    for (int p = 0; p < 4; p++) {
        float2 c0 = unpack2(acc2[p][0]);
        float2 c1 = unpack2(acc2[p][1]);
        float2 c2 = unpack2(acc2[p][2]);
        float2 c3 = unpack2(acc2[p][3]);
        float rowv[2][4] = {{c0.x, c1.x, c2.x, c3.x}, {c0.y, c1.y, c2.y, c3.y}};
#pragma unroll
        for (int h = 0; h < 2; h++) {
            int r = row0 + ty * 8 + p * 2 + h;
            if (r < n) {
                float o0 = rowv[h][0] + bv4.x, o1 = rowv[h][1] + bv4.y;
                float o2 = rowv[h][2] + bv4.z, o3 = rowv[h][3] + bv4.w;
                if (m == 0) {
                    *(float4*)&g_qt[(size_t)r * 128 + tx * 4] = make_float4(o0, o1, o2, o3);
                } else {
                    __nv_bfloat162 lo = __floats2bfloat162_rn(o0, o1);
                    __nv_bfloat162 hi = __floats2bfloat162_rn(o2, o3);
                    uint2 u;
                    u.x = *(unsigned*)&lo;
                    u.y = *(unsigned*)&hi;
                    *(uint2*)&g_v[(size_t)r * 128 + tx * 4] = u;
                }
            }
        }
    }
}

// ================= 7-9: CSR scan =================
__global__ void k_scan1(int n) {
    __shared__ int sh[1024];
    int tid = threadIdx.x;
    int i = blockIdx.x * 1024 + tid;
    int v = (i < n) ? g_cnt[i] : 0;
    sh[tid] = v;
    __syncthreads();
    for (int off = 1; off < 1024; off <<= 1) {
        int t = (tid >= off) ? sh[tid - off] : 0;
        __syncthreads();
        sh[tid] += t;
        __syncthreads();
    }
    if (i < n) g_rowptr[i] = sh[tid] - v;
    if (tid == 1023) g_blksum[blockIdx.x] = sh[1023];
}

__global__ void k_scan2(int nb, int n) {
    if (threadIdx.x == 0 && blockIdx.x == 0) {
        int acc = 0;
        for (int b = 0; b < nb; b++) { int t = g_blksum[b]; g_blksum[b] = acc; acc += t; }
        g_rowptr[n] = acc;
    }
}

__global__ void k_scan3(int n) {
    int i = blockIdx.x * 1024 + threadIdx.x;
    if (i < n) g_rowptr[i] += g_blksum[blockIdx.x];
}

// ================= 10: CSR scatter =================
__global__ void k_scatter(int e) {
    int i = blockIdx.x * blockDim.x + threadIdx.x;
    if (i < e) {
        int dst = g_edst[i];
        int pos = g_rowptr[dst] + atomicAdd(&g_cur[dst], 1);
        g_srcs[pos] = g_esrc[i];
    }
}

// ================= 11: attention (R9 core) =================
__device__ __forceinline__ float2 bf2f(unsigned u) {
    return __bfloat1622float2(*(__nv_bfloat162*)&u);
}

__global__ void __launch_bounds__(256) k_attn(int n) {
    int node = blockIdx.x * 8 + (threadIdx.x >> 5);
    if (node >= n) return;
    int lane = threadIdx.x & 31;
    int l15 = lane & 15;

    float4 qt = *(const float4*)&g_qt[(size_t)node * 128 + lane * 4];
    int beg = g_rowptr[node], end = g_rowptr[node + 1];

    const uint2* xb = (const uint2*)g_xb;
    const uint2* vb = (const uint2*)g_v;

    float denom = 0.f;
    float4 acc = make_float4(0.f, 0.f, 0.f, 0.f);

    int t = beg;
    for (; t + 4 <= end; t += 4) {
        int s0 = g_srcs[t + 0], s1 = g_srcs[t + 1], s2 = g_srcs[t + 2], s3 = g_srcs[t + 3];
        uint2 X0 = xb[(size_t)s0 * 16 + l15];
        uint2 X1 = xb[(size_t)s1 * 16 + l15];
        uint2 X2 = xb[(size_t)s2 * 16 + l15];
        uint2 X3 = xb[(size_t)s3 * 16 + l15];
        uint2 V0 = vb[(size_t)s0 * 32 + lane];
        uint2 V1 = vb[(size_t)s1 * 32 + lane];
        uint2 V2 = vb[(size_t)s2 * 32 + lane];
        uint2 V3 = vb[(size_t)s3 * 32 + lane];

        float2 a, b;
        a = bf2f(X0.x); b = bf2f(X0.y);
        float d0 = qt.x * a.x + qt.y * a.y + qt.z * b.x + qt.w * b.y;
        a = bf2f(X1.x); b = bf2f(X1.y);
        float d1 = qt.x * a.x + qt.y * a.y + qt.z * b.x + qt.w * b.y;
        a = bf2f(X2.x); b = bf2f(X2.y);
        float d2 = qt.x * a.x + qt.y * a.y + qt.z * b.x + qt.w * b.y;
        a = bf2f(X3.x); b = bf2f(X3.y);
        float d3 = qt.x * a.x + qt.y * a.y + qt.z * b.x + qt.w * b.y;
#pragma unroll
        for (int off = 8; off > 0; off >>= 1) {
            d0 += __shfl_xor_sync(0xffffffffu, d0, off);
            d1 += __shfl_xor_sync(0xffffffffu, d1, off);
            d2 += __shfl_xor_sync(0xffffffffu, d2, off);
            d3 += __shfl_xor_sync(0xffffffffu, d3, off);
        }
        float w0 = __expf(d0 * 0.125f);
        float w1 = __expf(d1 * 0.125f);
        float w2 = __expf(d2 * 0.125f);
        float w3 = __expf(d3 * 0.125f);
        denom += (w0 + w1) + (w2 + w3);

        a = bf2f(V0.x); b = bf2f(V0.y);
        acc.x = fmaf(w0, a.x, acc.x); acc.y = fmaf(w0, a.y, acc.y);
        acc.z = fmaf(w0, b.x, acc.z); acc.w = fmaf(w0, b.y, acc.w);
        a = bf2f(V1.x); b = bf2f(V1.y);
        acc.x = fmaf(w1, a.x, acc.x); acc.y = fmaf(w1, a.y, acc.y);
        acc.z = fmaf(w1, b.x, acc.z); acc.w = fmaf(w1, b.y, acc.w);
        a = bf2f(V2.x); b = bf2f(V2.y);
        acc.x = fmaf(w2, a.x, acc.x); acc.y = fmaf(w2, a.y, acc.y);
        acc.z = fmaf(w2, b.x, acc.z); acc.w = fmaf(w2, b.y, acc.w);
        a = bf2f(V3.x); b = bf2f(V3.y);
        acc.x = fmaf(w3, a.x, acc.x); acc.y = fmaf(w3, a.y, acc.y);
        acc.z = fmaf(w3, b.x, acc.z); acc.w = fmaf(w3, b.y, acc.w);
    }
    for (; t < end; t++) {
        int s = g_srcs[t];
        uint2 X = xb[(size_t)s * 16 + l15];
        uint2 V = vb[(size_t)s * 32 + lane];
        float2 a = bf2f(X.x);
        float2 b = bf2f(X.y);
        float d = qt.x * a.x + qt.y * a.y + qt.z * b.x + qt.w * b.y;
#pragma unroll
        for (int off = 8; off > 0; off >>= 1) d += __shfl_xor_sync(0xffffffffu, d, off);
        float w = __expf(d * 0.125f);
        denom += w;
        a = bf2f(V.x); b = bf2f(V.y);
        acc.x = fmaf(w, a.x, acc.x); acc.y = fmaf(w, a.y, acc.y);
        acc.z = fmaf(w, b.x, acc.z); acc.w = fmaf(w, b.y, acc.w);
    }
    float inv = 1.f / (denom + 1e-16f);
    acc.x *= inv; acc.y *= inv; acc.z *= inv; acc.w *= inv;
    ((float4*)g_agg)[(size_t)node * 32 + lane] = acc;
}

// ================= 12: out = agg@Wc + x@W2 + b2, f32x2 core, fused LN stats =================
__global__ void __launch_bounds__(256) k_final(const float* __restrict__ x,
                                               const float* __restrict__ Wc,
                                               float* __restrict__ out, int n) {
    __shared__ float Xs[32][132];
    __shared__ float Ws[32][64];
    __shared__ float rs[8], rss[8];

    int tx = threadIdx.x & 15;
    int ty = threadIdx.x >> 4;
    int row0 = blockIdx.x * 128;

    unsigned long long acc2[4][4];
#pragma unroll
    for (int p = 0; p < 4; p++)
#pragma unroll
        for (int j = 0; j < 4; j++) acc2[p][j] = 0ull;

    for (int kc = 0; kc < 6; kc++) {
#pragma unroll
        for (int it = 0; it < 4; it++) {
            int idx = threadIdx.x + it * 256;
            int r = idx >> 3, kq = idx & 7;
            float4 av = make_float4(0.f, 0.f, 0.f, 0.f);
            if (row0 + r < n) {
                if (kc < 4) av = ((const float4*)g_agg)[(size_t)(row0 + r) * 32 + kc * 8 + kq];
                else        av = ((const float4*)x)[(size_t)(row0 + r) * 16 + (kc - 4) * 8 + kq];
            }
            Xs[kq * 4 + 0][r] = av.x;
            Xs[kq * 4 + 1][r] = av.y;
            Xs[kq * 4 + 2][r] = av.z;
            Xs[kq * 4 + 3][r] = av.w;
        }
#pragma unroll
        for (int it = 0; it < 2; it++) {
            int idx = threadIdx.x + it * 256;
            int k = idx >> 4, c4 = idx & 15;
            float4 wv;
            if (kc < 4) wv = ((const float4*)Wc)[(kc * 32 + k) * 16 + c4];
            else        wv = ((const float4*)g_W2)[((kc - 4) * 32 + k) * 16 + c4];
            *(float4*)&Ws[k][c4 * 4] = wv;
        }
        __syncthreads();
#pragma unroll
        for (int k = 0; k < 32; k++) {
            float4 a0 = *(const float4*)&Xs[k][ty * 8];
            float4 a1 = *(const float4*)&Xs[k][ty * 8 + 4];
            float4 b  = *(const float4*)&Ws[k][tx * 4];
            unsigned long long A[4] = {pack2(a0.x, a0.y), pack2(a0.z, a0.w),
                                       pack2(a1.x, a1.y), pack2(a1.z, a1.w)};
            unsigned long long B[4] = {pack2(b.x, b.x), pack2(b.y, b.y),
                                       pack2(b.z, b.z), pack2(b.w, b.w)};
#pragma unroll
            for (int p = 0; p < 4; p++) {
                fma2(acc2[p][0], A[p], B[0]);
                fma2(acc2[p][1], A[p], B[1]);
                fma2(acc2[p][2], A[p], B[2]);
                fma2(acc2[p][3], A[p], B[3]);
            }
        }
        __syncthreads();
    }

    float4 b2 = *(const float4*)&g_b2[tx * 4];
    float s = 0.f, ss = 0.f;
#pragma unroll
    for (int p = 0; p < 4; p++) {
        float2 c0 = unpack2(acc2[p][0]);
        float2 c1 = unpack2(acc2[p][1]);
        float2 c2 = unpack2(acc2[p][2]);
        float2 c3 = unpack2(acc2[p][3]);
        float rowv[2][4] = {{c0.x, c1.x, c2.x, c3.x}, {c0.y, c1.y, c2.y, c3.y}};
#pragma unroll
        for (int h = 0; h < 2; h++) {
            int r = row0 + ty * 8 + p * 2 + h;
            if (r < n) {
                float4 o = make_float4(rowv[h][0] + b2.x, rowv[h][1] + b2.y,
                                       rowv[h][2] + b2.z, rowv[h][3] + b2.w);
                *(float4*)&out[(size_t)r * 64 + tx * 4] = o;
                s += (o.x + o.y) + (o.z + o.w);
                ss += o.x * o.x + o.y * o.y + o.z * o.z + o.w * o.w;
            }
        }
    }
#pragma unroll
    for (int off = 16; off > 0; off >>= 1) {
        s  += __shfl_xor_sync(0xffffffffu, s, off);
        ss += __shfl_xor_sync(0xffffffffu, ss, off);
    }
    int wid = threadIdx.x >> 5, lane = threadIdx.x & 31;
    if (lane == 0) { rs[wid] = s; rss[wid] = ss; }
    __syncthreads();
    if (threadIdx.x == 0) {
        double S = 0.0, SS = 0.0;
        for (int w = 0; w < 8; w++) { S += (double)rs[w]; SS += (double)rss[w]; }
        atomicAdd(&g_stats[0], S);
        atomicAdd(&g_stats[1], SS);
    }
}

// ================= 13: graph-level LayerNorm =================
__global__ void k_norm(float* __restrict__ out, const float* __restrict__ gamma,
                       const float* __restrict__ beta, int total) {
    int i = blockIdx.x * blockDim.x + threadIdx.x;
    if (i < total) {
        double M = (double)total;
        double mean = g_stats[0] / M;
        double var  = g_stats[1] / M - mean * mean;
        if (var < 0.0) var = 0.0;
        float stdv = (float)sqrt(var);
        float v = out[i];
        int d = i & 63;
        out[i] = (v - (float)mean) / (stdv + 1e-5f) * __ldg(&gamma[d]) + __ldg(&beta[d]);
    }
}

// ---------------- launch ----------------
extern "C" void kernel_launch(void* const* d_in, const int* in_sizes, int n_in,
                              void* d_out, int out_size) {
    const float* x    = (const float*)d_in[0];
    const void*  ei   = d_in[1];
    const float* Wq   = (const float*)d_in[2];
    const float* bq   = (const float*)d_in[3];
    const float* Wk   = (const float*)d_in[4];
    const float* Wv   = (const float*)d_in[6];
    const float* bv   = (const float*)d_in[7];
    const float* Wsk  = (const float*)d_in[8];
    const float* bsk  = (const float*)d_in[9];
    const float* Wc   = (const float*)d_in[10];
    const float* bc   = (const float*)d_in[11];
    const float* gam  = (const float*)d_in[12];
    const float* bet  = (const float*)d_in[13];
    float* out = (float*)d_out;

    int n = in_sizes[0] / 64;
    int e = in_sizes[1] / 2;

    k_init<<<(n + 255) / 256, 256>>>(n);                                  // #1
    k_detect<<<1, 32>>>(ei);                                              // #2
    k_prep<<<195, 256>>>(Wq, bq, Wk, Wsk, bsk, Wc, bc);                   // #3
    k_convert<<<(2 * e + 255) / 256, 256>>>(ei, e);                       // #4 <- capture slot
    k_xb<<<(n * 16 + 255) / 256, 256>>>(x, n);                            // #5
    k_gemm2<<<dim3((n + 63) / 64, 2), 256>>>(x, Wv, bv, n);               // #6
    int nb = (n + 1023) / 1024;
    k_scan1<<<nb, 1024>>>(n);                                             // #7
    k_scan2<<<1, 32>>>(nb, n);                                            // #8
    k_scan3<<<nb, 1024>>>(n);                                             // #9
    k_scatter<<<(e + 255) / 256, 256>>>(e);                               // #10
    k_attn<<<(n + 7) / 8, 256>>>(n);                                      // #11
    k_final<<<(n + 127) / 128, 256>>>(x, Wc, out, n);                     // #12
    k_norm<<<(n * 64 + 255) / 256, 256>>>(out, gam, bet, n * 64);         // #13
}

// round 14
// speedup vs baseline: 1.0800x; 1.0112x over previous
#include <cuda_runtime.h>
#include <cuda_bf16.h>
#include <math.h>

#define MAXN 50000
#define MAXE 800000

// ---------------- device scratch ----------------
__device__ __align__(16) float g_qt [(size_t)MAXN * 128];       // x@(WqWk^T) + gvec
__device__ __align__(16) __nv_bfloat16 g_xb[(size_t)MAXN * 64]; // x in bf16 (gather side)
__device__ __align__(16) __nv_bfloat16 g_v [(size_t)MAXN * 128];// projected v, bf16
__device__ __align__(16) float g_agg[(size_t)MAXN * 128];       // attention output
__device__ __align__(16) float g_M  [64 * 128];                 // Mcat = Wq Wk^T per head
__device__ __align__(16) float g_W2 [64 * 64];                  // Wskip @ Wc
__device__ float  g_gvec[128];                                   // Wk_h @ bq_h per head
__device__ float  g_b2[64];                                      // bskip@Wc + bc
__device__ int    g_esrc [MAXE];
__device__ int    g_edst [MAXE];
__device__ int    g_srcs [MAXE];
__device__ int    g_cnt  [MAXN];
__device__ int    g_cur  [MAXN];
__device__ int    g_rowptr[MAXN + 1];
__device__ int    g_blksum[64];
__device__ int    g_is64;
__device__ double g_stats[2];

// ---------------- packed fp32x2 helpers (Blackwell dual-MAC) ----------------
__device__ __forceinline__ void fma2(unsigned long long& acc, unsigned long long a,
                                     unsigned long long b) {
    asm("fma.rn.f32x2 %0, %1, %2, %3;" : "=l"(acc) : "l"(a), "l"(b), "l"(acc));
}
__device__ __forceinline__ unsigned long long pack2(float x, float y) {
    unsigned long long r;
    asm("mov.b64 %0, {%1, %2};" : "=l"(r) : "f"(x), "f"(y));
    return r;
}
__device__ __forceinline__ float2 unpack2(unsigned long long v) {
    float2 r;
    asm("mov.b64 {%0, %1}, %2;" : "=f"(r.x), "=f"(r.y) : "l"(v));
    return r;
}

// ================= 1: fused setup = init | detect | precomputes =================
__global__ void k_setup(const void* __restrict__ ei, int n,
                        const float* __restrict__ Wq, const float* __restrict__ bq,
                        const float* __restrict__ Wk,
                        const float* __restrict__ Wsk, const float* __restrict__ bsk,
                        const float* __restrict__ Wc, const float* __restrict__ bc) {
    int nInit = (n + 255) >> 8;
    int b = blockIdx.x;
    if (b < nInit) {
        // ---- init ----
        int i = b * 256 + threadIdx.x;
        if (i < n) { g_cnt[i] = 0; g_cur[i] = 0; }
        if (i == 0) { g_stats[0] = 0.0; g_stats[1] = 0.0; }
        return;
    }
    if (b == nInit) {
        // ---- edge dtype sniff ----
        if (threadIdx.x == 0) {
            const int* w = (const int*)ei;
            int all0 = 1;
            for (int i = 1; i < 64; i += 2) all0 &= (w[i] == 0);
            g_is64 = all0;
        }
        return;
    }
    // ---- precomputes: 4 threads/output + quad shuffle reduce ----
    int idx = (b - nInit - 1) * 256 + threadIdx.x;
    int g = idx >> 2, part = idx & 3;
    float s = 0.f;
    int valid = 0;
    float* dst = 0;
    if (g < 8192) {                      // Mcat
        int i = g >> 7, col = g & 127, h = col >> 6, j = col & 63;
        const float* wq = Wq + i * 128 + h * 64 + part * 16;
        const float* wk = Wk + j * 128 + h * 64 + part * 16;
#pragma unroll
        for (int c = 0; c < 16; c++) s = fmaf(wq[c], wk[c], s);
        dst = &g_M[g]; valid = 1;
    } else if (g < 12288) {              // W2
        int o = g - 8192, r = o >> 6, c = o & 63;
#pragma unroll
        for (int k = 0; k < 32; k++)
            s = fmaf(Wsk[r * 128 + part * 32 + k], Wc[(part * 32 + k) * 64 + c], s);
        dst = &g_W2[o]; valid = 1;
    } else if (g < 12352) {              // b2
        int c = g - 12288;
        if (part == 0) s = bc[c];
#pragma unroll
        for (int k = 0; k < 32; k++)
            s = fmaf(bsk[part * 32 + k], Wc[(part * 32 + k) * 64 + c], s);
        dst = &g_b2[c]; valid = 1;
    } else if (g < 12480) {              // gvec
        int o = g - 12352, h = o >> 6, i = o & 63;
#pragma unroll
        for (int j = 0; j < 16; j++)
            s = fmaf(Wk[i * 128 + h * 64 + part * 16 + j], bq[h * 64 + part * 16 + j], s);
        dst = &g_gvec[o]; valid = 1;
    }
    s += __shfl_xor_sync(0xffffffffu, s, 1);
    s += __shfl_xor_sync(0xffffffffu, s, 2);
    if (valid && part == 0) *dst = s;
}

// ================= 2: convert + fused dst histogram =================
__global__ void k_convert(const void* __restrict__ ei, int e) {
    int i = blockIdx.x * blockDim.x + threadIdx.x;
    if (i >= 2 * e) return;
    int v;
    if (g_is64) v = (int)((const long long*)ei)[i];
    else        v = ((const int*)ei)[i];
    if (i < e) g_esrc[i] = v;
    else { g_edst[i - e] = v; atomicAdd(&g_cnt[v], 1); }
}

// ================= 3: x -> bf16 copy =================
__global__ void k_xb(const float* __restrict__ x, int n) {
    int i = blockIdx.x * 256 + threadIdx.x;
    if (i < n * 16) {
        float4 xv = ((const float4*)x)[i];
        __nv_bfloat162 lo = __floats2bfloat162_rn(xv.x, xv.y);
        __nv_bfloat162 hi = __floats2bfloat162_rn(xv.z, xv.w);
        uint2 u;
        u.x = *(unsigned*)&lo;
        u.y = *(unsigned*)&hi;
        ((uint2*)g_xb)[i] = u;
    }
}

// ================= 4: qt | v GEMM, f32x2 core (PROFILED SLOT) =================
__global__ void __launch_bounds__(256) k_gemm2(
        const float* __restrict__ x,
        const float* __restrict__ Wv, const float* __restrict__ bv,
        int n) {
    __shared__ float Xs[32][68];
    __shared__ float Ws[32][128];
    int m = blockIdx.y;
    const float* W    = (m == 0) ? (const float*)g_M : Wv;
    const float* bias = (m == 0) ? (const float*)g_gvec : bv;

    int tx = threadIdx.x & 31;
    int ty = threadIdx.x >> 5;
    int row0 = blockIdx.x * 64;

    unsigned long long acc2[4][4];
#pragma unroll
    for (int p = 0; p < 4; p++)
#pragma unroll
        for (int j = 0; j < 4; j++) acc2[p][j] = 0ull;

    for (int kc = 0; kc < 2; kc++) {
#pragma unroll
        for (int it = 0; it < 2; it++) {
            int idx = threadIdx.x + it * 256;
            int r = idx >> 3, kq = idx & 7;
            float4 xv = make_float4(0.f, 0.f, 0.f, 0.f);
            if (row0 + r < n) xv = ((const float4*)x)[(size_t)(row0 + r) * 16 + kc * 8 + kq];
            Xs[kq * 4 + 0][r] = xv.x;
            Xs[kq * 4 + 1][r] = xv.y;
            Xs[kq * 4 + 2][r] = xv.z;
            Xs[kq * 4 + 3][r] = xv.w;
        }
#pragma unroll
        for (int it = 0; it < 4; it++) {
            int idx = threadIdx.x + it * 256;
            ((float4*)Ws)[idx] = ((const float4*)W)[kc * 1024 + idx];
        }
        __syncthreads();
#pragma unroll
        for (int k = 0; k < 32; k++) {
            float4 a0 = *(const float4*)&Xs[k][ty * 8];
            float4 a1 = *(const float4*)&Xs[k][ty * 8 + 4];
            float4 b  = *(const float4*)&Ws[k][tx * 4];
            unsigned long long A[4] = {pack2(a0.x, a0.y), pack2(a0.z, a0.w),
                                       pack2(a1.x, a1.y), pack2(a1.z, a1.w)};
            unsigned long long B[4] = {pack2(b.x, b.x), pack2(b.y, b.y),
                                       pack2(b.z, b.z), pack2(b.w, b.w)};
#pragma unroll
            for (int p = 0; p < 4; p++) {
                fma2(acc2[p][0], A[p], B[0]);
                fma2(acc2[p][1], A[p], B[1]);
                fma2(acc2[p][2], A[p], B[2]);
                fma2(acc2[p][3], A[p], B[3]);
            }
        }
        __syncthreads();
    }
    float4 bv4 = *(const float4*)&bias[tx * 4];
#pragma unroll
    for (int p = 0; p < 4; p++) {
        float2 c0 = unpack2(acc2[p][0]);
        float2 c1 = unpack2(acc2[p][1]);
        float2 c2 = unpack2(acc2[p][2]);
        float2 c3 = unpack2(acc2[p][3]);
        float rowv[2][4] = {{c0.x, c1.x, c2.x, c3.x}, {c0.y, c1.y, c2.y, c3.y}};
#pragma unroll
        for (int h = 0; h < 2; h++) {
            int r = row0 + ty * 8 + p * 2 + h;
            if (r < n) {
                float o0 = rowv[h][0] + bv4.x, o1 = rowv[h][1] + bv4.y;
                float o2 = rowv[h][2] + bv4.z, o3 = rowv[h][3] + bv4.w;
                if (m == 0) {
                    *(float4*)&g_qt[(size_t)r * 128 + tx * 4] = make_float4(o0, o1, o2, o3);
                } else {
                    __nv_bfloat162 lo = __floats2bfloat162_rn(o0, o1);
                    __nv_bfloat162 hi = __floats2bfloat162_rn(o2, o3);
                    uint2 u;
                    u.x = *(unsigned*)&lo;
                    u.y = *(unsigned*)&hi;
                    *(uint2*)&g_v[(size_t)r * 128 + tx * 4] = u;
                }
            }
        }
    }
}

// ================= 5: scan stage 1 =================
__global__ void k_scan1(int n) {
    __shared__ int sh[1024];
    int tid = threadIdx.x;
    int i = blockIdx.x * 1024 + tid;
    int v = (i < n) ? g_cnt[i] : 0;
    sh[tid] = v;
    __syncthreads();
    for (int off = 1; off < 1024; off <<= 1) {
        int t = (tid >= off) ? sh[tid - off] : 0;
        __syncthreads();
        sh[tid] += t;
        __syncthreads();
    }
    if (i < n) g_rowptr[i] = sh[tid] - v;
    if (tid == 1023) g_blksum[blockIdx.x] = sh[1023];
}

// ================= 6: scan stages 2+3 fused (each block computes its own prefix) =================
__global__ void __launch_bounds__(1024) k_scan23(int n, int nb) {
    __shared__ int pref;
    int bid = blockIdx.x;
    if (threadIdx.x == 0) {
        int acc = 0;
        for (int b = 0; b < bid; b++) acc += g_blksum[b];
        pref = acc;
        if (bid == nb - 1) g_rowptr[n] = acc + g_blksum[nb - 1];
    }
    __syncthreads();
    int i = bid * 1024 + threadIdx.x;
    if (i < n) g_rowptr[i] += pref;
}

// ================= 7: CSR scatter =================
__global__ void k_scatter(int e) {
    int i = blockIdx.x * blockDim.x + threadIdx.x;
    if (i < e) {
        int dst = g_edst[i];
        int pos = g_rowptr[dst] + atomicAdd(&g_cur[dst], 1);
        g_srcs[pos] = g_esrc[i];
    }
}

// ================= 8: attention =================
__device__ __forceinline__ float2 bf2f(unsigned u) {
    return __bfloat1622float2(*(__nv_bfloat162*)&u);
}

__global__ void __launch_bounds__(256) k_attn(int n) {
    int node = blockIdx.x * 8 + (threadIdx.x >> 5);
    if (node >= n) return;
    int lane = threadIdx.x & 31;
    int l15 = lane & 15;

    float4 qt = *(const float4*)&g_qt[(size_t)node * 128 + lane * 4];
    int beg = g_rowptr[node], end = g_rowptr[node + 1];

    const uint2* xb = (const uint2*)g_xb;
    const uint2* vb = (const uint2*)g_v;

    float denom = 0.f;
    float4 acc = make_float4(0.f, 0.f, 0.f, 0.f);

    int t = beg;
    for (; t + 4 <= end; t += 4) {
        int s0 = g_srcs[t + 0], s1 = g_srcs[t + 1], s2 = g_srcs[t + 2], s3 = g_srcs[t + 3];
        uint2 X0 = xb[(size_t)s0 * 16 + l15];
        uint2 X1 = xb[(size_t)s1 * 16 + l15];
        uint2 X2 = xb[(size_t)s2 * 16 + l15];
        uint2 X3 = xb[(size_t)s3 * 16 + l15];
        uint2 V0 = vb[(size_t)s0 * 32 + lane];
        uint2 V1 = vb[(size_t)s1 * 32 + lane];
        uint2 V2 = vb[(size_t)s2 * 32 + lane];
        uint2 V3 = vb[(size_t)s3 * 32 + lane];

        float2 a, b;
        a = bf2f(X0.x); b = bf2f(X0.y);
        float d0 = qt.x * a.x + qt.y * a.y + qt.z * b.x + qt.w * b.y;
        a = bf2f(X1.x); b = bf2f(X1.y);
        float d1 = qt.x * a.x + qt.y * a.y + qt.z * b.x + qt.w * b.y;
        a = bf2f(X2.x); b = bf2f(X2.y);
        float d2 = qt.x * a.x + qt.y * a.y + qt.z * b.x + qt.w * b.y;
        a = bf2f(X3.x); b = bf2f(X3.y);
        float d3 = qt.x * a.x + qt.y * a.y + qt.z * b.x + qt.w * b.y;
#pragma unroll
        for (int off = 8; off > 0; off >>= 1) {
            d0 += __shfl_xor_sync(0xffffffffu, d0, off);
            d1 += __shfl_xor_sync(0xffffffffu, d1, off);
            d2 += __shfl_xor_sync(0xffffffffu, d2, off);
            d3 += __shfl_xor_sync(0xffffffffu, d3, off);
        }
        float w0 = __expf(d0 * 0.125f);
        float w1 = __expf(d1 * 0.125f);
        float w2 = __expf(d2 * 0.125f);
        float w3 = __expf(d3 * 0.125f);
        denom += (w0 + w1) + (w2 + w3);

        a = bf2f(V0.x); b = bf2f(V0.y);
        acc.x = fmaf(w0, a.x, acc.x); acc.y = fmaf(w0, a.y, acc.y);
        acc.z = fmaf(w0, b.x, acc.z); acc.w = fmaf(w0, b.y, acc.w);
        a = bf2f(V1.x); b = bf2f(V1.y);
        acc.x = fmaf(w1, a.x, acc.x); acc.y = fmaf(w1, a.y, acc.y);
        acc.z = fmaf(w1, b.x, acc.z); acc.w = fmaf(w1, b.y, acc.w);
        a = bf2f(V2.x); b = bf2f(V2.y);
        acc.x = fmaf(w2, a.x, acc.x); acc.y = fmaf(w2, a.y, acc.y);
        acc.z = fmaf(w2, b.x, acc.z); acc.w = fmaf(w2, b.y, acc.w);
        a = bf2f(V3.x); b = bf2f(V3.y);
        acc.x = fmaf(w3, a.x, acc.x); acc.y = fmaf(w3, a.y, acc.y);
        acc.z = fmaf(w3, b.x, acc.z); acc.w = fmaf(w3, b.y, acc.w);
    }
    for (; t < end; t++) {
        int s = g_srcs[t];
        uint2 X = xb[(size_t)s * 16 + l15];
        uint2 V = vb[(size_t)s * 32 + lane];
        float2 a = bf2f(X.x);
        float2 b = bf2f(X.y);
        float d = qt.x * a.x + qt.y * a.y + qt.z * b.x + qt.w * b.y;
#pragma unroll
        for (int off = 8; off > 0; off >>= 1) d += __shfl_xor_sync(0xffffffffu, d, off);
        float w = __expf(d * 0.125f);
        denom += w;
        a = bf2f(V.x); b = bf2f(V.y);
        acc.x = fmaf(w, a.x, acc.x); acc.y = fmaf(w, a.y, acc.y);
        acc.z = fmaf(w, b.x, acc.z); acc.w = fmaf(w, b.y, acc.w);
    }
    float inv = 1.f / (denom + 1e-16f);
    acc.x *= inv; acc.y *= inv; acc.z *= inv; acc.w *= inv;
    ((float4*)g_agg)[(size_t)node * 32 + lane] = acc;
}

// ================= 9: out = agg@Wc + x@W2 + b2, f32x2 core, fused LN stats =================
__global__ void __launch_bounds__(256) k_final(const float* __restrict__ x,
                                               const float* __restrict__ Wc,
                                               float* __restrict__ out, int n) {
    __shared__ float Xs[32][132];
    __shared__ float Ws[32][64];
    __shared__ float rs[8], rss[8];

    int tx = threadIdx.x & 15;
    int ty = threadIdx.x >> 4;
    int row0 = blockIdx.x * 128;

    unsigned long long acc2[4][4];
#pragma unroll
    for (int p = 0; p < 4; p++)
#pragma unroll
        for (int j = 0; j < 4; j++) acc2[p][j] = 0ull;

    for (int kc = 0; kc < 6; kc++) {
#pragma unroll
        for (int it = 0; it < 4; it++) {
            int idx = threadIdx.x + it * 256;
            int r = idx >> 3, kq = idx & 7;
            float4 av = make_float4(0.f, 0.f, 0.f, 0.f);
            if (row0 + r < n) {
                if (kc < 4) av = ((const float4*)g_agg)[(size_t)(row0 + r) * 32 + kc * 8 + kq];
                else        av = ((const float4*)x)[(size_t)(row0 + r) * 16 + (kc - 4) * 8 + kq];
            }
            Xs[kq * 4 + 0][r] = av.x;
            Xs[kq * 4 + 1][r] = av.y;
            Xs[kq * 4 + 2][r] = av.z;
            Xs[kq * 4 + 3][r] = av.w;
        }
#pragma unroll
        for (int it = 0; it < 2; it++) {
            int idx = threadIdx.x + it * 256;
            int k = idx >> 4, c4 = idx & 15;
            float4 wv;
            if (kc < 4) wv = ((const float4*)Wc)[(kc * 32 + k) * 16 + c4];
            else        wv = ((const float4*)g_W2)[((kc - 4) * 32 + k) * 16 + c4];
            *(float4*)&Ws[k][c4 * 4] = wv;
        }
        __syncthreads();
#pragma unroll
        for (int k = 0; k < 32; k++) {
            float4 a0 = *(const float4*)&Xs[k][ty * 8];
            float4 a1 = *(const float4*)&Xs[k][ty * 8 + 4];
            float4 b  = *(const float4*)&Ws[k][tx * 4];
            unsigned long long A[4] = {pack2(a0.x, a0.y), pack2(a0.z, a0.w),
                                       pack2(a1.x, a1.y), pack2(a1.z, a1.w)};
            unsigned long long B[4] = {pack2(b.x, b.x), pack2(b.y, b.y),
                                       pack2(b.z, b.z), pack2(b.w, b.w)};
#pragma unroll
            for (int p = 0; p < 4; p++) {
                fma2(acc2[p][0], A[p], B[0]);
                fma2(acc2[p][1], A[p], B[1]);
                fma2(acc2[p][2], A[p], B[2]);
                fma2(acc2[p][3], A[p], B[3]);
            }
        }
        __syncthreads();
    }

    float4 b2 = *(const float4*)&g_b2[tx * 4];
    float s = 0.f, ss = 0.f;
#pragma unroll
    for (int p = 0; p < 4; p++) {
        float2 c0 = unpack2(acc2[p][0]);
        float2 c1 = unpack2(acc2[p][1]);
        float2 c2 = unpack2(acc2[p][2]);
        float2 c3 = unpack2(acc2[p][3]);
        float rowv[2][4] = {{c0.x, c1.x, c2.x, c3.x}, {c0.y, c1.y, c2.y, c3.y}};
#pragma unroll
        for (int h = 0; h < 2; h++) {
            int r = row0 + ty * 8 + p * 2 + h;
            if (r < n) {
                float4 o = make_float4(rowv[h][0] + b2.x, rowv[h][1] + b2.y,
                                       rowv[h][2] + b2.z, rowv[h][3] + b2.w);
                *(float4*)&out[(size_t)r * 64 + tx * 4] = o;
                s += (o.x + o.y) + (o.z + o.w);
                ss += o.x * o.x + o.y * o.y + o.z * o.z + o.w * o.w;
            }
        }
    }
#pragma unroll
    for (int off = 16; off > 0; off >>= 1) {
        s  += __shfl_xor_sync(0xffffffffu, s, off);
        ss += __shfl_xor_sync(0xffffffffu, ss, off);
    }
    int wid = threadIdx.x >> 5, lane = threadIdx.x & 31;
    if (lane == 0) { rs[wid] = s; rss[wid] = ss; }
    __syncthreads();
    if (threadIdx.x == 0) {
        double S = 0.0, SS = 0.0;
        for (int w = 0; w < 8; w++) { S += (double)rs[w]; SS += (double)rss[w]; }
        atomicAdd(&g_stats[0], S);
        atomicAdd(&g_stats[1], SS);
    }
}

// ================= 10: graph-level LayerNorm =================
__global__ void k_norm(float* __restrict__ out, const float* __restrict__ gamma,
                       const float* __restrict__ beta, int total) {
    int i = blockIdx.x * blockDim.x + threadIdx.x;
    if (i < total) {
        double M = (double)total;
        double mean = g_stats[0] / M;
        double var  = g_stats[1] / M - mean * mean;
        if (var < 0.0) var = 0.0;
        float stdv = (float)sqrt(var);
        float v = out[i];
        int d = i & 63;
        out[i] = (v - (float)mean) / (stdv + 1e-5f) * __ldg(&gamma[d]) + __ldg(&beta[d]);
    }
}

// ---------------- launch ----------------
extern "C" void kernel_launch(void* const* d_in, const int* in_sizes, int n_in,
                              void* d_out, int out_size) {
    const float* x    = (const float*)d_in[0];
    const void*  ei   = d_in[1];
    const float* Wq   = (const float*)d_in[2];
    const float* bq   = (const float*)d_in[3];
    const float* Wk   = (const float*)d_in[4];
    const float* Wv   = (const float*)d_in[6];
    const float* bv   = (const float*)d_in[7];
    const float* Wsk  = (const float*)d_in[8];
    const float* bsk  = (const float*)d_in[9];
    const float* Wc   = (const float*)d_in[10];
    const float* bc   = (const float*)d_in[11];
    const float* gam  = (const float*)d_in[12];
    const float* bet  = (const float*)d_in[13];
    float* out = (float*)d_out;

    int n = in_sizes[0] / 64;
    int e = in_sizes[1] / 2;

    int nInit = (n + 255) / 256;
    k_setup<<<nInit + 1 + 195, 256>>>(ei, n, Wq, bq, Wk, Wsk, bsk, Wc, bc);  // #1
    k_convert<<<(2 * e + 255) / 256, 256>>>(ei, e);                           // #2
    k_xb<<<(n * 16 + 255) / 256, 256>>>(x, n);                                // #3
    k_gemm2<<<dim3((n + 63) / 64, 2), 256>>>(x, Wv, bv, n);                   // #4 <- capture
    int nb = (n + 1023) / 1024;
    k_scan1<<<nb, 1024>>>(n);                                                 // #5
    k_scan23<<<nb, 1024>>>(n, nb);                                            // #6
    k_scatter<<<(e + 255) / 256, 256>>>(e);                                   // #7
    k_attn<<<(n + 7) / 8, 256>>>(n);                                          // #8
    k_final<<<(n + 127) / 128, 256>>>(x, Wc, out, n);                         // #9
    k_norm<<<(n * 64 + 255) / 256, 256>>>(out, gam, bet, n * 64);             // #10
}